// round 3
// baseline (speedup 1.0000x reference)
#include <cuda_runtime.h>

// LIF neuron recurrence, fully parallel across B*N neurons, serial over T.
//   out[t]  = (mem > 1.0f) ? 1 : 0
//   mem     = (0.5f*mem + syn) * (1 - out[t])
//   syn     = in[t]
// inputs: [T=100, B=256, N=2048] fp32 contiguous; output same shape.
//
// R3: revert R2's streaming cache hints (measured -3% DRAM util — evict-first
// stores hurt L2 write coalescing). Back to 512 blocks x 256 threads (best
// config, 61.5us kernel). T baked in at compile time, unroll 10 to deepen
// load front-batching. This workload is pinned at the mixed R/W HBM ceiling
// (419.4MB fixed traffic -> 52.4us floor at 8TB/s spec).

constexpr int T_STEPS = 100;

__global__ void __launch_bounds__(256) lif_kernel(
    const float4* __restrict__ in,
    float4* __restrict__ out,
    int n4)
{
    int i = blockIdx.x * blockDim.x + threadIdx.x;
    if (i >= n4) return;

    float4 mem = make_float4(0.f, 0.f, 0.f, 0.f);
    float4 syn = make_float4(0.f, 0.f, 0.f, 0.f);

    size_t idx = (size_t)i;
    const size_t stride = (size_t)n4;

    #pragma unroll 10
    for (int t = 0; t < T_STEPS; ++t, idx += stride) {
        float4 x = in[idx];

        float4 o;
        o.x = (mem.x > 1.0f) ? 1.0f : 0.0f;
        o.y = (mem.y > 1.0f) ? 1.0f : 0.0f;
        o.z = (mem.z > 1.0f) ? 1.0f : 0.0f;
        o.w = (mem.w > 1.0f) ? 1.0f : 0.0f;

        out[idx] = o;

        mem.x = (0.5f * mem.x + syn.x) * (1.0f - o.x);
        mem.y = (0.5f * mem.y + syn.y) * (1.0f - o.y);
        mem.z = (0.5f * mem.z + syn.z) * (1.0f - o.z);
        mem.w = (0.5f * mem.w + syn.w) * (1.0f - o.w);

        syn = x;
    }
}

extern "C" void kernel_launch(void* const* d_in, const int* in_sizes, int n_in,
                              void* d_out, int out_size)
{
    const float* in = (const float*)d_in[0];
    float* out = (float*)d_out;

    const int BN = in_sizes[0] / T_STEPS;  // 524288
    const int n4 = BN / 4;                 // 131072 float4 lanes

    const int threads = 256;
    const int blocks = (n4 + threads - 1) / threads;  // 512

    lif_kernel<<<blocks, threads>>>(
        (const float4*)in, (float4*)out, n4);
}

// round 4
// speedup vs baseline: 1.0574x; 1.0574x over previous
#include <cuda_runtime.h>

// LIF neuron recurrence, fully parallel across B*N neurons, serial over T.
//   out[t]  = (mem > 1.0f) ? 1 : 0
//   mem     = (0.5f*mem + syn) * (1 - out[t])
//   syn     = in[t]
// inputs: [T=100, B=256, N=2048] fp32 contiguous; output same shape.
//
// R4: 256-bit loads/stores (ld/st.global.v8.f32, sm_100a+). DRAM was pinned at
// exactly 75.9% / 6.0 TB/s across all 128-bit configs — testing whether the
// L1tex/LTS wavefront path (~6300 B/cyc) is the binder. 8 floats/thread,
// 65536 threads = 512 blocks x 128.

constexpr int T_STEPS = 100;

struct __align__(32) float8 { float v[8]; };

__device__ __forceinline__ void ldg256(const float8* p, float8& r) {
    asm volatile(
        "ld.global.v8.f32 {%0, %1, %2, %3, %4, %5, %6, %7}, [%8];"
        : "=f"(r.v[0]), "=f"(r.v[1]), "=f"(r.v[2]), "=f"(r.v[3]),
          "=f"(r.v[4]), "=f"(r.v[5]), "=f"(r.v[6]), "=f"(r.v[7])
        : "l"(p));
}

__device__ __forceinline__ void stg256(float8* p, const float8& r) {
    asm volatile(
        "st.global.v8.f32 [%0], {%1, %2, %3, %4, %5, %6, %7, %8};"
        :: "l"(p),
           "f"(r.v[0]), "f"(r.v[1]), "f"(r.v[2]), "f"(r.v[3]),
           "f"(r.v[4]), "f"(r.v[5]), "f"(r.v[6]), "f"(r.v[7])
        : "memory");
}

__global__ void __launch_bounds__(128) lif_kernel(
    const float8* __restrict__ in,
    float8* __restrict__ out,
    int n8)
{
    int i = blockIdx.x * blockDim.x + threadIdx.x;
    if (i >= n8) return;

    float mem[8], syn[8];
    #pragma unroll
    for (int k = 0; k < 8; ++k) { mem[k] = 0.f; syn[k] = 0.f; }

    size_t idx = (size_t)i;
    const size_t stride = (size_t)n8;

    #pragma unroll 4
    for (int t = 0; t < T_STEPS; ++t, idx += stride) {
        float8 x;
        ldg256(&in[idx], x);

        float8 o;
        #pragma unroll
        for (int k = 0; k < 8; ++k)
            o.v[k] = (mem[k] > 1.0f) ? 1.0f : 0.0f;

        stg256(&out[idx], o);

        #pragma unroll
        for (int k = 0; k < 8; ++k) {
            mem[k] = (0.5f * mem[k] + syn[k]) * (1.0f - o.v[k]);
            syn[k] = x.v[k];
        }
    }
}

extern "C" void kernel_launch(void* const* d_in, const int* in_sizes, int n_in,
                              void* d_out, int out_size)
{
    const float* in = (const float*)d_in[0];
    float* out = (float*)d_out;

    const int BN = in_sizes[0] / T_STEPS;  // 524288
    const int n8 = BN / 8;                 // 65536 lanes of 8 floats

    const int threads = 128;
    const int blocks = (n8 + threads - 1) / threads;  // 512

    lif_kernel<<<blocks, threads>>>(
        (const float8*)in, (float8*)out, n8);
}